// round 9
// baseline (speedup 1.0000x reference)
#include <cuda_runtime.h>

// ---------------------------------------------------------------------------
// ClassifierHetero — live dataflow only (conv stack is dead code in reference):
//   hg[b] = [mean(h_comp|g=b), mean2(h_port|g=b), mean(h_net|g=b)]  -> [64,4]
//   out   = relu(relu(hg@Wc1+bc1)@Wc2+bc2)@Wc3+bc3                  -> [64,10]
//
// R7: single fused kernel, block-role specialization.
//   blocks 64..655: warp-aggregated segment reduce (as R5)
//   blocks 0..63  : per-graph MLP. Prefetch weights to L2 DURING the reduce,
//                   spin on a done-counter, then compute with L2-hot loads.
// All __device__ state returns to zero each replay (consume-and-reset).
// ---------------------------------------------------------------------------

#define NB    64   // graphs
#define NRED  592  // reduce blocks
#define NBLK  (NRED + NB)

__device__ float g_sum[4 * NB];  // [0]=comp, [1]=port.x, [2]=port.y, [3]=net
__device__ int   g_cnt[3 * NB];  // [0]=comp, [1]=port,   [2]=net
__device__ int   g_done;         // reduce-blocks-finished counter
__device__ int   g_ack;          // MLP-blocks-finished counter

__device__ __forceinline__ float warp_sum_f(float v) {
#pragma unroll
    for (int o = 16; o; o >>= 1) v += __shfl_xor_sync(0xffffffffu, v, o);
    return v;
}

__device__ __forceinline__ void l2_prefetch(const void* p) {
    asm volatile("prefetch.global.L2 [%0];" :: "l"(p));
}

__global__ void __launch_bounds__(256, 8)
hx_fused_kernel(const float* __restrict__ h_comp,
                const int*   __restrict__ gid_comp, int nc,
                const float* __restrict__ h_port,
                const int*   __restrict__ gid_port, int np,
                const float* __restrict__ h_net,
                const int*   __restrict__ gid_net,  int nn,
                const float* __restrict__ Wc1, const float* __restrict__ bc1,
                const float* __restrict__ Wc2, const float* __restrict__ bc2,
                const float* __restrict__ Wc3, const float* __restrict__ bc3,
                float* __restrict__ out) {
    // =====================================================================
    // Role: REDUCE (blocks 64..655)
    // =====================================================================
    if (blockIdx.x >= NB) {
        __shared__ float s_sum[4 * NB];
        __shared__ int   s_cnt[3 * NB];
        for (int i = threadIdx.x; i < 4 * NB; i += blockDim.x) s_sum[i] = 0.0f;
        for (int i = threadIdx.x; i < 3 * NB; i += blockDim.x) s_cnt[i] = 0;
        __syncthreads();

        const int lane   = threadIdx.x & 31;
        const int rb     = blockIdx.x - NB;
        const int warp_g = (rb * blockDim.x + threadIdx.x) >> 5;
        const int nwarps = (NRED * blockDim.x) >> 5;

        const int wc_c = (nc + 31) >> 5;
        const int wc_p = (np + 31) >> 5;
        const int wc_n = (nn + 31) >> 5;
        const int wc_total = wc_c + wc_p + wc_n;

        for (int w = warp_g; w < wc_total; w += nwarps) {
            if (w < wc_c) {
                int idx = (w << 5) + lane;
                bool act = idx < nc;
                unsigned m = __ballot_sync(0xffffffffu, act);
                int   g = act ? gid_comp[idx] : -1;
                float v = act ? h_comp[idx]   : 0.0f;
                int g0 = __shfl_sync(0xffffffffu, g, 0);
                if (__all_sync(0xffffffffu, !act || g == g0)) {
                    v = warp_sum_f(v);
                    if (lane == 0) {
                        atomicAdd(&s_sum[0 * NB + g0], v);
                        atomicAdd(&s_cnt[0 * NB + g0], __popc(m));
                    }
                } else if (act) {
                    atomicAdd(&s_sum[0 * NB + g], v);
                    atomicAdd(&s_cnt[0 * NB + g], 1);
                }
            } else if (w < wc_c + wc_p) {
                int c = w - wc_c;
                int idx = (c << 5) + lane;
                bool act = idx < np;
                unsigned m = __ballot_sync(0xffffffffu, act);
                int g = act ? gid_port[idx] : -1;
                float2 v = act ? __ldg(reinterpret_cast<const float2*>(h_port) + idx)
                               : make_float2(0.0f, 0.0f);
                int g0 = __shfl_sync(0xffffffffu, g, 0);
                if (__all_sync(0xffffffffu, !act || g == g0)) {
                    float sx = warp_sum_f(v.x);
                    float sy = warp_sum_f(v.y);
                    if (lane == 0) {
                        atomicAdd(&s_sum[1 * NB + g0], sx);
                        atomicAdd(&s_sum[2 * NB + g0], sy);
                        atomicAdd(&s_cnt[1 * NB + g0], __popc(m));
                    }
                } else if (act) {
                    atomicAdd(&s_sum[1 * NB + g], v.x);
                    atomicAdd(&s_sum[2 * NB + g], v.y);
                    atomicAdd(&s_cnt[1 * NB + g], 1);
                }
            } else {
                int c = w - wc_c - wc_p;
                int idx = (c << 5) + lane;
                bool act = idx < nn;
                unsigned m = __ballot_sync(0xffffffffu, act);
                int   g = act ? gid_net[idx] : -1;
                float v = act ? h_net[idx]   : 0.0f;
                int g0 = __shfl_sync(0xffffffffu, g, 0);
                if (__all_sync(0xffffffffu, !act || g == g0)) {
                    v = warp_sum_f(v);
                    if (lane == 0) {
                        atomicAdd(&s_sum[3 * NB + g0], v);
                        atomicAdd(&s_cnt[2 * NB + g0], __popc(m));
                    }
                } else if (act) {
                    atomicAdd(&s_sum[3 * NB + g], v);
                    atomicAdd(&s_cnt[2 * NB + g], 1);
                }
            }
        }
        __syncthreads();

        for (int i = threadIdx.x; i < 4 * NB; i += blockDim.x)
            if (s_sum[i] != 0.0f) atomicAdd(&g_sum[i], s_sum[i]);
        for (int i = threadIdx.x; i < 3 * NB; i += blockDim.x)
            if (s_cnt[i] != 0) atomicAdd(&g_cnt[i], s_cnt[i]);
        __syncthreads();

        if (threadIdx.x == 0) {
            __threadfence();
            atomicAdd(&g_done, 1);
        }
        return;
    }

    // =====================================================================
    // Role: MLP (blocks 0..63, one graph row each; compute uses tid<128)
    // =====================================================================
    const int b = blockIdx.x;
    const int j = threadIdx.x;

    // --- Prefetch all classifier weights into L2 while reduce runs ---
    {
        // Wc2: 128*128 floats = 512 lines of 128B
        for (int i = threadIdx.x; i < 512; i += blockDim.x)
            l2_prefetch(Wc2 + i * 32);
        // Wc3: 128*10 floats = 40 lines
        for (int i = threadIdx.x; i < 40; i += blockDim.x)
            l2_prefetch(Wc3 + i * 32);
        // Wc1: 4*128 = 16 lines; biases: few lines
        if (threadIdx.x < 16) l2_prefetch(Wc1 + threadIdx.x * 32);
        if (threadIdx.x < 4)  l2_prefetch(bc1 + threadIdx.x * 32);
        if (threadIdx.x < 4)  l2_prefetch(bc2 + threadIdx.x * 32);
        if (threadIdx.x == 0) l2_prefetch(bc3);
    }

    // --- Wait for all reduce blocks ---
    if (threadIdx.x == 0) {
        while (atomicAdd(&g_done, 0) < NRED) __nanosleep(128);
        __threadfence();
    }
    __syncthreads();

    __shared__ float shg[4];
    __shared__ float sh1[128];
    __shared__ float sh2[128];

    // Consume + reset accumulator entries (L1-bypass loads; entries were
    // written by L2 atomics).
    if (j == 0) {
        float s0 = __ldcg(&g_sum[0 * NB + b]);
        float s1 = __ldcg(&g_sum[1 * NB + b]);
        float s2 = __ldcg(&g_sum[2 * NB + b]);
        float s3 = __ldcg(&g_sum[3 * NB + b]);
        float c0 = (float)__ldcg(&g_cnt[0 * NB + b]);
        float c1 = (float)__ldcg(&g_cnt[1 * NB + b]);
        float c2 = (float)__ldcg(&g_cnt[2 * NB + b]);
        shg[0] = s0 / fmaxf(c0, 1.0f);
        shg[1] = s1 / fmaxf(c1, 1.0f);
        shg[2] = s2 / fmaxf(c1, 1.0f);
        shg[3] = s3 / fmaxf(c2, 1.0f);
        g_sum[0 * NB + b] = 0.0f;
        g_sum[1 * NB + b] = 0.0f;
        g_sum[2 * NB + b] = 0.0f;
        g_sum[3 * NB + b] = 0.0f;
        g_cnt[0 * NB + b] = 0;
        g_cnt[1 * NB + b] = 0;
        g_cnt[2 * NB + b] = 0;
    }
    __syncthreads();

    if (j < 128) {
        const float hg0 = shg[0], hg1 = shg[1], hg2 = shg[2], hg3 = shg[3];

        float v = hg0 * Wc1[0 * 128 + j] + hg1 * Wc1[1 * 128 + j] +
                  hg2 * Wc1[2 * 128 + j] + hg3 * Wc1[3 * 128 + j] + bc1[j];
        sh1[j] = fmaxf(v, 0.0f);
    }
    __syncthreads();

    if (j < 128) {
        // h2 = relu(sh1 @ Wc2 + bc2): 128 independent L2-hot loads
        const float* __restrict__ w2 = Wc2 + j;
        float a0 = 0.0f, a1 = 0.0f, a2 = 0.0f, a3 = 0.0f;
#pragma unroll
        for (int k = 0; k < 128; k += 4) {
            a0 = fmaf(sh1[k + 0], w2[(k + 0) * 128], a0);
            a1 = fmaf(sh1[k + 1], w2[(k + 1) * 128], a1);
            a2 = fmaf(sh1[k + 2], w2[(k + 2) * 128], a2);
            a3 = fmaf(sh1[k + 3], w2[(k + 3) * 128], a3);
        }
        sh2[j] = fmaxf((a0 + a1) + (a2 + a3) + bc2[j], 0.0f);
    }
    __syncthreads();

    if (j < 10) {
        const float* __restrict__ w3 = Wc3 + j;
        float o0 = 0.0f, o1 = 0.0f, o2 = 0.0f, o3 = 0.0f;
#pragma unroll
        for (int k = 0; k < 128; k += 4) {
            o0 = fmaf(sh2[k + 0], w3[(k + 0) * 10], o0);
            o1 = fmaf(sh2[k + 1], w3[(k + 1) * 10], o1);
            o2 = fmaf(sh2[k + 2], w3[(k + 2) * 10], o2);
            o3 = fmaf(sh2[k + 3], w3[(k + 3) * 10], o3);
        }
        out[b * 10 + j] = (o0 + o1) + (o2 + o3) + bc3[j];
    }
    __syncthreads();

    // Replay-state reset: last MLP block to finish zeroes the counters.
    if (threadIdx.x == 0) {
        __threadfence();
        int old = atomicAdd(&g_ack, 1);
        if (old == NB - 1) {
            atomicExch(&g_done, 0);
            atomicExch(&g_ack, 0);
        }
    }
}

extern "C" void kernel_launch(void* const* d_in, const int* in_sizes, int n_in,
                              void* d_out, int out_size) {
    // metadata order: 0 h_comp  1 h_port  2 h_net | 3..6 edges (dead)
    // 7..9 gid_{comp,port,net} | 10..21 conv weights (dead)
    // 22 Wc1 23 bc1 24 Wc2 25 bc2 26 Wc3 27 bc3
    const float* h_comp  = (const float*)d_in[0];
    const float* h_port  = (const float*)d_in[1];
    const float* h_net   = (const float*)d_in[2];
    const int* gid_comp  = (const int*)d_in[7];
    const int* gid_port  = (const int*)d_in[8];
    const int* gid_net   = (const int*)d_in[9];
    const float* Wc1 = (const float*)d_in[22];
    const float* bc1 = (const float*)d_in[23];
    const float* Wc2 = (const float*)d_in[24];
    const float* bc2 = (const float*)d_in[25];
    const float* Wc3 = (const float*)d_in[26];
    const float* bc3 = (const float*)d_in[27];
    float* out = (float*)d_out;

    const int nc = in_sizes[0];
    const int np = in_sizes[1] / 2;
    const int nn = in_sizes[2];

    hx_fused_kernel<<<NBLK, 256>>>(h_comp, gid_comp, nc,
                                   h_port, gid_port, np,
                                   h_net,  gid_net,  nn,
                                   Wc1, bc1, Wc2, bc2, Wc3, bc3, out);
}